// round 2
// baseline (speedup 1.0000x reference)
#include <cuda_runtime.h>
#include <cuda_bf16.h>
#include <cstdint>

// ---------------------------------------------------------------------------
// S4Block on GB300:
//   K0: convert B, C to bf16
//   K1: xB = x @ B^T            (bf16 mma.sync, fp32 accum)  [32768,1024]x[128,1024]^T
//   K2: s_t = tanh(s_{t-1} A^T + xB_t)  sequential scan, f32x2 FFMA2, 1 CTA/batch
//   K3: out = states @ C^T      (bf16 mma.sync, fp32 accum)  [32768,128]x[1024,128]^T
//   K4: y = LN(out + D*x + x) * gamma + beta   (row-wise, fused residual)
// ---------------------------------------------------------------------------

#define BATCH   16
#define SEQ     2048
#define DM      1024
#define DS      128
#define MTOT    (BATCH * SEQ)          // 32768
#define LN_EPS  1e-5f

// Scratch (device globals; no allocation allowed)
__device__ float          g_xB[MTOT * DS];             // 16 MB
__device__ __nv_bfloat16  g_states[MTOT * DS];         // 8 MB
__device__ __nv_bfloat16  g_Bbf[DS * DM];              // 256 KB
__device__ __nv_bfloat16  g_Cbf[DM * DS];              // 256 KB
__device__ float          g_t[(size_t)MTOT * DM];      // 128 MB

// ---------------------------------------------------------------------------
// helpers
// ---------------------------------------------------------------------------
__device__ __forceinline__ float tanh_fast(float x) {
    float y;
    asm("tanh.approx.f32 %0, %1;" : "=f"(y) : "f"(x));
    return y;
}

typedef unsigned long long u64;
__device__ __forceinline__ u64 pack2(float x, float y) {
    u64 r;
    asm("mov.b64 %0, {%1,%2};" : "=l"(r) : "f"(x), "f"(y));
    return r;
}
__device__ __forceinline__ float2 unpack2(u64 v) {
    float2 f;
    asm("mov.b64 {%0,%1}, %2;" : "=f"(f.x), "=f"(f.y) : "l"(v));
    return f;
}
// packed 2xfp32 FMA (FFMA2): acc = a*b + acc
__device__ __forceinline__ void fma2(u64& acc, u64 a, u64 b) {
    asm("fma.rn.f32x2 %0, %1, %2, %3;" : "=l"(acc) : "l"(a), "l"(b), "l"(acc));
}

__device__ __forceinline__ void mma_bf16(float* d,
                                         uint32_t a0, uint32_t a1, uint32_t a2, uint32_t a3,
                                         uint32_t b0, uint32_t b1) {
    asm("mma.sync.aligned.m16n8k16.row.col.f32.bf16.bf16.f32 "
        "{%0,%1,%2,%3}, {%4,%5,%6,%7}, {%8,%9}, {%0,%1,%2,%3};"
        : "+f"(d[0]), "+f"(d[1]), "+f"(d[2]), "+f"(d[3])
        : "r"(a0), "r"(a1), "r"(a2), "r"(a3), "r"(b0), "r"(b1));
}

// Shared-tile MMA over one [128m x 32k] x [128n x 32k] chunk.
// Tiles are stored row-padded to 40 bf16 (80B) -> conflict-free frag loads.
#define TPAD 40
__device__ __forceinline__ void mma_tile(const __nv_bfloat16* As,
                                         const __nv_bfloat16* Bs,
                                         float acc[2][8][4]) {
    const int lane = threadIdx.x & 31;
    const int warp = threadIdx.x >> 5;
    const int wm = warp >> 1;          // 0..3 -> 32-row strip
    const int wn = warp & 1;           // 0..1 -> 64-col strip
    const int lr = lane >> 2;          // 0..7
    const int lc = (lane & 3) * 2;     // 0,2,4,6
#pragma unroll
    for (int kk = 0; kk < 32; kk += 16) {
        uint32_t a[2][4];
#pragma unroll
        for (int mi = 0; mi < 2; mi++) {
            const __nv_bfloat16* p = As + (wm * 32 + mi * 16 + lr) * TPAD + kk + lc;
            a[mi][0] = *(const uint32_t*)p;
            a[mi][1] = *(const uint32_t*)(p + 8 * TPAD);
            a[mi][2] = *(const uint32_t*)(p + 8);
            a[mi][3] = *(const uint32_t*)(p + 8 * TPAD + 8);
        }
        uint32_t b[8][2];
#pragma unroll
        for (int ni = 0; ni < 8; ni++) {
            const __nv_bfloat16* p = Bs + (wn * 64 + ni * 8 + lr) * TPAD + kk + lc;
            b[ni][0] = *(const uint32_t*)p;
            b[ni][1] = *(const uint32_t*)(p + 8);
        }
#pragma unroll
        for (int mi = 0; mi < 2; mi++)
#pragma unroll
            for (int ni = 0; ni < 8; ni++)
                mma_bf16(acc[mi][ni], a[mi][0], a[mi][1], a[mi][2], a[mi][3],
                         b[ni][0], b[ni][1]);
    }
}

// ---------------------------------------------------------------------------
// K0: convert B, C to bf16
// ---------------------------------------------------------------------------
__global__ void k0_convert(const float* __restrict__ B, const float* __restrict__ C) {
    int idx = blockIdx.x * 256 + threadIdx.x;
    if (idx < DS * DM) g_Bbf[idx] = __float2bfloat16(B[idx]);
    if (idx < DM * DS) g_Cbf[idx] = __float2bfloat16(C[idx]);
}

// ---------------------------------------------------------------------------
// K1: xB = x @ B^T.  Grid: 256 CTAs (m-tiles of 128). N = 128 (one tile).
// ---------------------------------------------------------------------------
__global__ void __launch_bounds__(256) k1_xB(const float* __restrict__ x) {
    __shared__ __nv_bfloat16 As[128 * TPAD];
    __shared__ __nv_bfloat16 Bs[128 * TPAD];
    const int t = threadIdx.x;
    const int m0 = blockIdx.x * 128;

    float acc[2][8][4];
#pragma unroll
    for (int i = 0; i < 2; i++)
#pragma unroll
        for (int j = 0; j < 8; j++)
#pragma unroll
            for (int k = 0; k < 4; k++) acc[i][j][k] = 0.f;

    for (int kt = 0; kt < DM; kt += 32) {
        // load x tile [128 x 32] fp32 -> bf16
#pragma unroll
        for (int pass = 0; pass < 4; pass++) {
            int r = pass * 32 + (t >> 3);
            int c = (t & 7) * 4;
            float4 v = *(const float4*)(x + (size_t)(m0 + r) * DM + kt + c);
            __nv_bfloat162 p0 = __floats2bfloat162_rn(v.x, v.y);
            __nv_bfloat162 p1 = __floats2bfloat162_rn(v.z, v.w);
            *(__nv_bfloat162*)&As[r * TPAD + c]     = p0;
            *(__nv_bfloat162*)&As[r * TPAD + c + 2] = p1;
        }
        // load B tile [128 x 32] bf16 (2 threads per row, 16 bf16 = 2 uint4 each)
        {
            int r = t >> 1;
            int half = t & 1;
            const __nv_bfloat16* src = g_Bbf + r * DM + kt + half * 16;
            uint4 v0 = *(const uint4*)(src);
            uint4 v1 = *(const uint4*)(src + 8);
            *(uint4*)&Bs[r * TPAD + half * 16]     = v0;
            *(uint4*)&Bs[r * TPAD + half * 16 + 8] = v1;
        }
        __syncthreads();
        mma_tile(As, Bs, acc);
        __syncthreads();
    }

    // epilogue -> g_xB [MTOT x 128] fp32
    const int lane = t & 31, warp = t >> 5;
    const int wm = warp >> 1, wn = warp & 1;
    const int lr = lane >> 2, lc = (lane & 3) * 2;
#pragma unroll
    for (int mi = 0; mi < 2; mi++)
#pragma unroll
        for (int ni = 0; ni < 8; ni++) {
            int row = m0 + wm * 32 + mi * 16 + lr;
            int col = wn * 64 + ni * 8 + lc;
            float* o0 = g_xB + (size_t)row * DS + col;
            float* o1 = g_xB + (size_t)(row + 8) * DS + col;
            *(float2*)o0 = make_float2(acc[mi][ni][0], acc[mi][ni][1]);
            *(float2*)o1 = make_float2(acc[mi][ni][2], acc[mi][ni][3]);
        }
}

// ---------------------------------------------------------------------------
// K2: recurrence. 16 CTAs (one per batch) x 512 threads.
// Thread (i = t>>2, p = t&3): output state element i, j-chunk p (32 j's).
// A rows cached in registers as f32x2, state ping-pong in SMEM.
// ---------------------------------------------------------------------------
__global__ void __launch_bounds__(512, 1) k2_scan(const float* __restrict__ A) {
    const int b = blockIdx.x;
    const int t = threadIdx.x;
    const int i = t >> 2;
    const int p = t & 3;

    __shared__ float s_sh[2][DS];

    // A[i][p*32 .. p*32+31] as 16 packed f32x2
    u64 a[16];
#pragma unroll
    for (int u = 0; u < 16; u++) {
        float2 v = *(const float2*)(A + i * DS + p * 32 + 2 * u);
        a[u] = pack2(v.x, v.y);
    }

    if (t < DS) { s_sh[0][t] = 0.f; s_sh[1][t] = 0.f; }
    __syncthreads();

    const float* xb = g_xB + (size_t)b * SEQ * DS;
    __nv_bfloat16* so = g_states + (size_t)b * SEQ * DS;

    float xb_cur = (p == 0) ? xb[i] : 0.f;

    for (int tt = 0; tt < SEQ; tt++) {
        float xb_next = 0.f;
        if (p == 0 && tt + 1 < SEQ) xb_next = xb[(tt + 1) * DS + i];

        const float4* sv = (const float4*)(s_sh[tt & 1] + p * 32);
        u64 acc[4];
        acc[0] = acc[1] = acc[2] = acc[3] = 0ull;   // {0.f, 0.f}
#pragma unroll
        for (int u2 = 0; u2 < 8; u2++) {
            float4 s4 = sv[u2];
            u64 s01 = pack2(s4.x, s4.y);
            u64 s23 = pack2(s4.z, s4.w);
            fma2(acc[(2 * u2) & 3], a[2 * u2], s01);
            fma2(acc[(2 * u2 + 1) & 3], a[2 * u2 + 1], s23);
        }
        float2 r0 = unpack2(acc[0]), r1 = unpack2(acc[1]);
        float2 r2 = unpack2(acc[2]), r3 = unpack2(acc[3]);
        float v = (r0.x + r0.y) + (r1.x + r1.y) + (r2.x + r2.y) + (r3.x + r3.y);
        v += __shfl_xor_sync(0xffffffffu, v, 1);
        v += __shfl_xor_sync(0xffffffffu, v, 2);
        if (p == 0) {
            float s = tanh_fast(v + xb_cur);
            s_sh[(tt + 1) & 1][i] = s;
            so[tt * DS + i] = __float2bfloat16(s);
        }
        xb_cur = xb_next;
        __syncthreads();
    }
}

// ---------------------------------------------------------------------------
// K3: out = states @ C^T.  Grid: (256 m-tiles, 8 n-tiles). K = 128.
// ---------------------------------------------------------------------------
__global__ void __launch_bounds__(256) k3_out() {
    __shared__ __nv_bfloat16 As[128 * TPAD];
    __shared__ __nv_bfloat16 Bs[128 * TPAD];
    const int t = threadIdx.x;
    const int m0 = blockIdx.x * 128;
    const int n0 = blockIdx.y * 128;

    float acc[2][8][4];
#pragma unroll
    for (int i = 0; i < 2; i++)
#pragma unroll
        for (int j = 0; j < 8; j++)
#pragma unroll
            for (int k = 0; k < 4; k++) acc[i][j][k] = 0.f;

    for (int kt = 0; kt < DS; kt += 32) {
        {   // states tile [128 x 32] bf16 (2 threads per row, 16 bf16 each)
            int r = t >> 1;
            int half = t & 1;
            const __nv_bfloat16* src = g_states + (size_t)(m0 + r) * DS + kt + half * 16;
            uint4 v0 = *(const uint4*)(src);
            uint4 v1 = *(const uint4*)(src + 8);
            *(uint4*)&As[r * TPAD + half * 16]     = v0;
            *(uint4*)&As[r * TPAD + half * 16 + 8] = v1;
        }
        {   // C tile [128 x 32] bf16
            int r = t >> 1;
            int half = t & 1;
            const __nv_bfloat16* src = g_Cbf + (n0 + r) * DS + kt + half * 16;
            uint4 v0 = *(const uint4*)(src);
            uint4 v1 = *(const uint4*)(src + 8);
            *(uint4*)&Bs[r * TPAD + half * 16]     = v0;
            *(uint4*)&Bs[r * TPAD + half * 16 + 8] = v1;
        }
        __syncthreads();
        mma_tile(As, Bs, acc);
        __syncthreads();
    }

    const int lane = t & 31, warp = t >> 5;
    const int wm = warp >> 1, wn = warp & 1;
    const int lr = lane >> 2, lc = (lane & 3) * 2;
#pragma unroll
    for (int mi = 0; mi < 2; mi++)
#pragma unroll
        for (int ni = 0; ni < 8; ni++) {
            int row = m0 + wm * 32 + mi * 16 + lr;
            int col = n0 + wn * 64 + ni * 8 + lc;
            float* o0 = g_t + (size_t)row * DM + col;
            float* o1 = g_t + (size_t)(row + 8) * DM + col;
            *(float2*)o0 = make_float2(acc[mi][ni][0], acc[mi][ni][1]);
            *(float2*)o1 = make_float2(acc[mi][ni][2], acc[mi][ni][3]);
        }
}

// ---------------------------------------------------------------------------
// K4: y = LN(out + D*x + x) * gamma + beta.  One CTA (256 thr) per row.
// ---------------------------------------------------------------------------
__global__ void __launch_bounds__(256) k4_ln(const float* __restrict__ x,
                                             const float* __restrict__ D,
                                             const float* __restrict__ gamma,
                                             const float* __restrict__ beta,
                                             float* __restrict__ y) {
    const int m = blockIdx.x;
    const int t = threadIdx.x;
    const int c = t * 4;

    float4 o4 = *(const float4*)(g_t + (size_t)m * DM + c);
    float4 x4 = *(const float4*)(x + (size_t)m * DM + c);
    float4 d4 = *(const float4*)(D + c);

    float4 v;
    v.x = o4.x + d4.x * x4.x + x4.x;
    v.y = o4.y + d4.y * x4.y + x4.y;
    v.z = o4.z + d4.z * x4.z + x4.z;
    v.w = o4.w + d4.w * x4.w + x4.w;

    float s = v.x + v.y + v.z + v.w;
    float q = v.x * v.x + v.y * v.y + v.z * v.z + v.w * v.w;
#pragma unroll
    for (int o = 16; o > 0; o >>= 1) {
        s += __shfl_xor_sync(0xffffffffu, s, o);
        q += __shfl_xor_sync(0xffffffffu, q, o);
    }
    __shared__ float ss[8], qq[8];
    __shared__ float mu_s, rs_s;
    if ((t & 31) == 0) { ss[t >> 5] = s; qq[t >> 5] = q; }
    __syncthreads();
    if (t == 0) {
        float S = 0.f, Q = 0.f;
#pragma unroll
        for (int w = 0; w < 8; w++) { S += ss[w]; Q += qq[w]; }
        float mu = S * (1.f / DM);
        float var = Q * (1.f / DM) - mu * mu;
        mu_s = mu;
        rs_s = rsqrtf(var + LN_EPS);
    }
    __syncthreads();
    float mu = mu_s, rs = rs_s;

    float4 g4 = *(const float4*)(gamma + c);
    float4 b4 = *(const float4*)(beta + c);
    float4 out;
    out.x = (v.x - mu) * rs * g4.x + b4.x;
    out.y = (v.y - mu) * rs * g4.y + b4.y;
    out.z = (v.z - mu) * rs * g4.z + b4.z;
    out.w = (v.w - mu) * rs * g4.w + b4.w;
    *(float4*)(y + (size_t)m * DM + c) = out;
}

// ---------------------------------------------------------------------------
extern "C" void kernel_launch(void* const* d_in, const int* in_sizes, int n_in,
                              void* d_out, int out_size) {
    const float* x     = (const float*)d_in[0];
    const float* A     = (const float*)d_in[1];
    const float* B     = (const float*)d_in[2];
    const float* C     = (const float*)d_in[3];
    const float* D     = (const float*)d_in[4];
    const float* gamma = (const float*)d_in[5];
    const float* beta  = (const float*)d_in[6];
    float* y = (float*)d_out;

    k0_convert<<<512, 256>>>(B, C);
    k1_xB<<<MTOT / 128, 256>>>(x);
    k2_scan<<<BATCH, 512>>>(A);
    k3_out<<<dim3(MTOT / 128, DM / 128), 256>>>();
    k4_ln<<<MTOT, 256>>>(x, D, gamma, beta, y);
}

// round 3
// speedup vs baseline: 1.0770x; 1.0770x over previous
#include <cuda_runtime.h>
#include <cuda_bf16.h>
#include <cstdint>

// ---------------------------------------------------------------------------
// S4Block on GB300:
//   K0: convert B, C to bf16
//   K1: xB = x @ B^T            (bf16 mma.sync, fp32 accum)
//   K2: s_t = tanh(s_{t-1} A^T + xB_t)  scan; cp.async-staged xB, f32x2 FMA
//   K3: out = states @ C^T      (bf16 mma.sync, fp32 accum)
//   K4: y = LN(out + D*x + x) * gamma + beta
// ---------------------------------------------------------------------------

#define BATCH   16
#define SEQ     2048
#define DM      1024
#define DS      128
#define MTOT    (BATCH * SEQ)          // 32768
#define LN_EPS  1e-5f
#define CH      16                     // xB staging chunk (steps)

// Scratch (device globals; no allocation allowed)
__device__ float          g_xB[MTOT * DS];             // 16 MB
__device__ __nv_bfloat16  g_states[MTOT * DS];         // 8 MB
__device__ __nv_bfloat16  g_Bbf[DS * DM];              // 256 KB
__device__ __nv_bfloat16  g_Cbf[DM * DS];              // 256 KB
__device__ float          g_t[(size_t)MTOT * DM];      // 128 MB

// ---------------------------------------------------------------------------
// helpers
// ---------------------------------------------------------------------------
__device__ __forceinline__ float tanh_fast(float x) {
    float y;
    asm("tanh.approx.f32 %0, %1;" : "=f"(y) : "f"(x));
    return y;
}

typedef unsigned long long u64;
__device__ __forceinline__ u64 pack2(float x, float y) {
    u64 r;
    asm("mov.b64 %0, {%1,%2};" : "=l"(r) : "f"(x), "f"(y));
    return r;
}
__device__ __forceinline__ float2 unpack2(u64 v) {
    float2 f;
    asm("mov.b64 {%0,%1}, %2;" : "=f"(f.x), "=f"(f.y) : "l"(v));
    return f;
}
// packed 2xfp32 FMA (FFMA2): acc = a*b + acc
__device__ __forceinline__ void fma2(u64& acc, u64 a, u64 b) {
    asm("fma.rn.f32x2 %0, %1, %2, %3;" : "=l"(acc) : "l"(a), "l"(b), "l"(acc));
}

__device__ __forceinline__ void cp16(void* smem, const void* gmem) {
    uint32_t s = (uint32_t)__cvta_generic_to_shared(smem);
    asm volatile("cp.async.cg.shared.global [%0], [%1], 16;" :: "r"(s), "l"(gmem));
}
__device__ __forceinline__ void cp_commit() {
    asm volatile("cp.async.commit_group;");
}
template <int N>
__device__ __forceinline__ void cp_wait() {
    asm volatile("cp.async.wait_group %0;" :: "n"(N));
}

__device__ __forceinline__ void mma_bf16(float* d,
                                         uint32_t a0, uint32_t a1, uint32_t a2, uint32_t a3,
                                         uint32_t b0, uint32_t b1) {
    asm("mma.sync.aligned.m16n8k16.row.col.f32.bf16.bf16.f32 "
        "{%0,%1,%2,%3}, {%4,%5,%6,%7}, {%8,%9}, {%0,%1,%2,%3};"
        : "+f"(d[0]), "+f"(d[1]), "+f"(d[2]), "+f"(d[3])
        : "r"(a0), "r"(a1), "r"(a2), "r"(a3), "r"(b0), "r"(b1));
}

// Shared-tile MMA over one [128m x 32k] x [128n x 32k] chunk.
#define TPAD 40
__device__ __forceinline__ void mma_tile(const __nv_bfloat16* As,
                                         const __nv_bfloat16* Bs,
                                         float acc[2][8][4]) {
    const int lane = threadIdx.x & 31;
    const int warp = threadIdx.x >> 5;
    const int wm = warp >> 1;
    const int wn = warp & 1;
    const int lr = lane >> 2;
    const int lc = (lane & 3) * 2;
#pragma unroll
    for (int kk = 0; kk < 32; kk += 16) {
        uint32_t a[2][4];
#pragma unroll
        for (int mi = 0; mi < 2; mi++) {
            const __nv_bfloat16* p = As + (wm * 32 + mi * 16 + lr) * TPAD + kk + lc;
            a[mi][0] = *(const uint32_t*)p;
            a[mi][1] = *(const uint32_t*)(p + 8 * TPAD);
            a[mi][2] = *(const uint32_t*)(p + 8);
            a[mi][3] = *(const uint32_t*)(p + 8 * TPAD + 8);
        }
        uint32_t b[8][2];
#pragma unroll
        for (int ni = 0; ni < 8; ni++) {
            const __nv_bfloat16* p = Bs + (wn * 64 + ni * 8 + lr) * TPAD + kk + lc;
            b[ni][0] = *(const uint32_t*)p;
            b[ni][1] = *(const uint32_t*)(p + 8);
        }
#pragma unroll
        for (int mi = 0; mi < 2; mi++)
#pragma unroll
            for (int ni = 0; ni < 8; ni++)
                mma_bf16(acc[mi][ni], a[mi][0], a[mi][1], a[mi][2], a[mi][3],
                         b[ni][0], b[ni][1]);
    }
}

// ---------------------------------------------------------------------------
// K0: convert B, C to bf16
// ---------------------------------------------------------------------------
__global__ void k0_convert(const float* __restrict__ B, const float* __restrict__ C) {
    int idx = blockIdx.x * 256 + threadIdx.x;
    if (idx < DS * DM) g_Bbf[idx] = __float2bfloat16(B[idx]);
    if (idx < DM * DS) g_Cbf[idx] = __float2bfloat16(C[idx]);
}

// ---------------------------------------------------------------------------
// K1: xB = x @ B^T.  Grid: 256 CTAs (m-tiles of 128). N = 128 (one tile).
// ---------------------------------------------------------------------------
__global__ void __launch_bounds__(256) k1_xB(const float* __restrict__ x) {
    __shared__ __nv_bfloat16 As[128 * TPAD];
    __shared__ __nv_bfloat16 Bs[128 * TPAD];
    const int t = threadIdx.x;
    const int m0 = blockIdx.x * 128;

    float acc[2][8][4];
#pragma unroll
    for (int i = 0; i < 2; i++)
#pragma unroll
        for (int j = 0; j < 8; j++)
#pragma unroll
            for (int k = 0; k < 4; k++) acc[i][j][k] = 0.f;

    for (int kt = 0; kt < DM; kt += 32) {
#pragma unroll
        for (int pass = 0; pass < 4; pass++) {
            int r = pass * 32 + (t >> 3);
            int c = (t & 7) * 4;
            float4 v = *(const float4*)(x + (size_t)(m0 + r) * DM + kt + c);
            __nv_bfloat162 p0 = __floats2bfloat162_rn(v.x, v.y);
            __nv_bfloat162 p1 = __floats2bfloat162_rn(v.z, v.w);
            *(__nv_bfloat162*)&As[r * TPAD + c]     = p0;
            *(__nv_bfloat162*)&As[r * TPAD + c + 2] = p1;
        }
        {
            int r = t >> 1;
            int half = t & 1;
            const __nv_bfloat16* src = g_Bbf + r * DM + kt + half * 16;
            uint4 v0 = *(const uint4*)(src);
            uint4 v1 = *(const uint4*)(src + 8);
            *(uint4*)&Bs[r * TPAD + half * 16]     = v0;
            *(uint4*)&Bs[r * TPAD + half * 16 + 8] = v1;
        }
        __syncthreads();
        mma_tile(As, Bs, acc);
        __syncthreads();
    }

    const int lane = t & 31, warp = t >> 5;
    const int wm = warp >> 1, wn = warp & 1;
    const int lr = lane >> 2, lc = (lane & 3) * 2;
#pragma unroll
    for (int mi = 0; mi < 2; mi++)
#pragma unroll
        for (int ni = 0; ni < 8; ni++) {
            int row = m0 + wm * 32 + mi * 16 + lr;
            int col = wn * 64 + ni * 8 + lc;
            float* o0 = g_xB + (size_t)row * DS + col;
            float* o1 = g_xB + (size_t)(row + 8) * DS + col;
            *(float2*)o0 = make_float2(acc[mi][ni][0], acc[mi][ni][1]);
            *(float2*)o1 = make_float2(acc[mi][ni][2], acc[mi][ni][3]);
        }
}

// ---------------------------------------------------------------------------
// K2: recurrence. 16 CTAs (one per batch) x 512 threads.
// Thread (i = t>>2, p = t&3): output element i, j-chunk p (32 j's).
// xB staged into SMEM via double-buffered cp.async chunks of CH steps.
// ---------------------------------------------------------------------------
__global__ void __launch_bounds__(512, 1) k2_scan(const float* __restrict__ A) {
    const int b = blockIdx.x;
    const int t = threadIdx.x;
    const int i = t >> 2;
    const int p = t & 3;

    __shared__ float s_sh[2][DS];
    __shared__ float xb_sh[2][CH * DS];    // 2 x 8KB

    // A[i][p*32 .. p*32+31] as 16 packed f32x2
    u64 a[16];
#pragma unroll
    for (int u = 0; u < 16; u++) {
        float2 v = *(const float2*)(A + i * DS + p * 32 + 2 * u);
        a[u] = pack2(v.x, v.y);
    }

    const float* xb = g_xB + (size_t)b * SEQ * DS;
    __nv_bfloat16* so = g_states + (size_t)b * SEQ * DS;

    // preload chunks 0 and 1 (each: 512 threads x 16B = 8KB)
    cp16(&xb_sh[0][t * 4], xb + t * 4);
    cp_commit();
    cp16(&xb_sh[1][t * 4], xb + CH * DS + t * 4);
    cp_commit();

    if (t < DS) { s_sh[0][t] = 0.f; s_sh[1][t] = 0.f; }
    __syncthreads();

    for (int c = 0; c < SEQ / CH; c++) {
        cp_wait<1>();          // chunk c resident
        __syncthreads();       // visible to all threads

        const float* xbc = xb_sh[c & 1];
#pragma unroll
        for (int k = 0; k < CH; k++) {
            const int tt = c * CH + k;
            const u64* sv = (const u64*)(s_sh[tt & 1] + p * 32);
            u64 acc0 = 0ull, acc1 = 0ull, acc2 = 0ull, acc3 = 0ull;
#pragma unroll
            for (int u2 = 0; u2 < 4; u2++) {
                fma2(acc0, a[4 * u2 + 0], sv[4 * u2 + 0]);
                fma2(acc1, a[4 * u2 + 1], sv[4 * u2 + 1]);
                fma2(acc2, a[4 * u2 + 2], sv[4 * u2 + 2]);
                fma2(acc3, a[4 * u2 + 3], sv[4 * u2 + 3]);
            }
            float2 r0 = unpack2(acc0), r1 = unpack2(acc1);
            float2 r2 = unpack2(acc2), r3 = unpack2(acc3);
            float v = ((r0.x + r0.y) + (r1.x + r1.y)) + ((r2.x + r2.y) + (r3.x + r3.y));
            v += __shfl_xor_sync(0xffffffffu, v, 1);
            v += __shfl_xor_sync(0xffffffffu, v, 2);
            if (p == 0) {
                float s = tanh_fast(v + xbc[k * DS + i]);
                s_sh[(tt + 1) & 1][i] = s;
                so[tt * DS + i] = __float2bfloat16(s);
            }
            __syncthreads();
        }

        // prefetch chunk c+2 into the buffer just consumed
        if (c + 2 < SEQ / CH)
            cp16(&xb_sh[c & 1][t * 4], xb + (size_t)(c + 2) * CH * DS + t * 4);
        cp_commit();
    }
}

// ---------------------------------------------------------------------------
// K3: out = states @ C^T.  Grid: (256 m-tiles, 8 n-tiles). K = 128.
// ---------------------------------------------------------------------------
__global__ void __launch_bounds__(256) k3_out() {
    __shared__ __nv_bfloat16 As[128 * TPAD];
    __shared__ __nv_bfloat16 Bs[128 * TPAD];
    const int t = threadIdx.x;
    const int m0 = blockIdx.x * 128;
    const int n0 = blockIdx.y * 128;

    float acc[2][8][4];
#pragma unroll
    for (int i = 0; i < 2; i++)
#pragma unroll
        for (int j = 0; j < 8; j++)
#pragma unroll
            for (int k = 0; k < 4; k++) acc[i][j][k] = 0.f;

    for (int kt = 0; kt < DS; kt += 32) {
        {
            int r = t >> 1;
            int half = t & 1;
            const __nv_bfloat16* src = g_states + (size_t)(m0 + r) * DS + kt + half * 16;
            uint4 v0 = *(const uint4*)(src);
            uint4 v1 = *(const uint4*)(src + 8);
            *(uint4*)&As[r * TPAD + half * 16]     = v0;
            *(uint4*)&As[r * TPAD + half * 16 + 8] = v1;
        }
        {
            int r = t >> 1;
            int half = t & 1;
            const __nv_bfloat16* src = g_Cbf + (n0 + r) * DS + kt + half * 16;
            uint4 v0 = *(const uint4*)(src);
            uint4 v1 = *(const uint4*)(src + 8);
            *(uint4*)&Bs[r * TPAD + half * 16]     = v0;
            *(uint4*)&Bs[r * TPAD + half * 16 + 8] = v1;
        }
        __syncthreads();
        mma_tile(As, Bs, acc);
        __syncthreads();
    }

    const int lane = t & 31, warp = t >> 5;
    const int wm = warp >> 1, wn = warp & 1;
    const int lr = lane >> 2, lc = (lane & 3) * 2;
#pragma unroll
    for (int mi = 0; mi < 2; mi++)
#pragma unroll
        for (int ni = 0; ni < 8; ni++) {
            int row = m0 + wm * 32 + mi * 16 + lr;
            int col = n0 + wn * 64 + ni * 8 + lc;
            float* o0 = g_t + (size_t)row * DM + col;
            float* o1 = g_t + (size_t)(row + 8) * DM + col;
            *(float2*)o0 = make_float2(acc[mi][ni][0], acc[mi][ni][1]);
            *(float2*)o1 = make_float2(acc[mi][ni][2], acc[mi][ni][3]);
        }
}

// ---------------------------------------------------------------------------
// K4: y = LN(out + D*x + x) * gamma + beta.  One CTA (256 thr) per row.
// ---------------------------------------------------------------------------
__global__ void __launch_bounds__(256) k4_ln(const float* __restrict__ x,
                                             const float* __restrict__ D,
                                             const float* __restrict__ gamma,
                                             const float* __restrict__ beta,
                                             float* __restrict__ y) {
    const int m = blockIdx.x;
    const int t = threadIdx.x;
    const int c = t * 4;

    float4 o4 = *(const float4*)(g_t + (size_t)m * DM + c);
    float4 x4 = *(const float4*)(x + (size_t)m * DM + c);
    float4 d4 = *(const float4*)(D + c);

    float4 v;
    v.x = o4.x + d4.x * x4.x + x4.x;
    v.y = o4.y + d4.y * x4.y + x4.y;
    v.z = o4.z + d4.z * x4.z + x4.z;
    v.w = o4.w + d4.w * x4.w + x4.w;

    float s = v.x + v.y + v.z + v.w;
    float q = v.x * v.x + v.y * v.y + v.z * v.z + v.w * v.w;
#pragma unroll
    for (int o = 16; o > 0; o >>= 1) {
        s += __shfl_xor_sync(0xffffffffu, s, o);
        q += __shfl_xor_sync(0xffffffffu, q, o);
    }
    __shared__ float ss[8], qq[8];
    __shared__ float mu_s, rs_s;
    if ((t & 31) == 0) { ss[t >> 5] = s; qq[t >> 5] = q; }
    __syncthreads();
    if (t == 0) {
        float S = 0.f, Q = 0.f;
#pragma unroll
        for (int w = 0; w < 8; w++) { S += ss[w]; Q += qq[w]; }
        float mu = S * (1.f / DM);
        float var = Q * (1.f / DM) - mu * mu;
        mu_s = mu;
        rs_s = rsqrtf(var + LN_EPS);
    }
    __syncthreads();
    float mu = mu_s, rs = rs_s;

    float4 g4 = *(const float4*)(gamma + c);
    float4 b4 = *(const float4*)(beta + c);
    float4 out;
    out.x = (v.x - mu) * rs * g4.x + b4.x;
    out.y = (v.y - mu) * rs * g4.y + b4.y;
    out.z = (v.z - mu) * rs * g4.z + b4.z;
    out.w = (v.w - mu) * rs * g4.w + b4.w;
    *(float4*)(y + (size_t)m * DM + c) = out;
}

// ---------------------------------------------------------------------------
extern "C" void kernel_launch(void* const* d_in, const int* in_sizes, int n_in,
                              void* d_out, int out_size) {
    const float* x     = (const float*)d_in[0];
    const float* A     = (const float*)d_in[1];
    const float* B     = (const float*)d_in[2];
    const float* C     = (const float*)d_in[3];
    const float* D     = (const float*)d_in[4];
    const float* gamma = (const float*)d_in[5];
    const float* beta  = (const float*)d_in[6];
    float* y = (float*)d_out;

    k0_convert<<<512, 256>>>(B, C);
    k1_xB<<<MTOT / 128, 256>>>(x);
    k2_scan<<<BATCH, 512>>>(A);
    k3_out<<<dim3(MTOT / 128, DM / 128), 256>>>();
    k4_ln<<<MTOT, 256>>>(x, D, gamma, beta, y);
}

// round 4
// speedup vs baseline: 4.2535x; 3.9493x over previous
#include <cuda_runtime.h>
#include <cuda_bf16.h>
#include <cstdint>

// ---------------------------------------------------------------------------
// S4Block on GB300:
//   K0: convert B, C to bf16
//   K1: xB = x @ B^T            (bf16 mma.sync, fp32 accum)
//   K2: s_t = tanh(s_{t-1} A^T + xB_t)  scan; 128 thr/CTA, full-dot per thread,
//       A in registers (f32x2), state broadcast via LDS.128, no shfl/conflicts
//   K3: out = states @ C^T      (bf16 mma.sync, fp32 accum)
//   K4: y = LN(out + D*x + x) * gamma + beta
// ---------------------------------------------------------------------------

#define BATCH   16
#define SEQ     2048
#define DM      1024
#define DS      128
#define MTOT    (BATCH * SEQ)          // 32768
#define LN_EPS  1e-5f
#define CH      16                     // xB staging chunk (steps)

// Scratch (device globals; no allocation allowed)
__device__ float          g_xB[MTOT * DS];             // 16 MB
__device__ __nv_bfloat16  g_states[MTOT * DS];         // 8 MB
__device__ __nv_bfloat16  g_Bbf[DS * DM];              // 256 KB
__device__ __nv_bfloat16  g_Cbf[DM * DS];              // 256 KB
__device__ float          g_t[(size_t)MTOT * DM];      // 128 MB

// ---------------------------------------------------------------------------
// helpers
// ---------------------------------------------------------------------------
__device__ __forceinline__ float tanh_fast(float x) {
    float y;
    asm("tanh.approx.f32 %0, %1;" : "=f"(y) : "f"(x));
    return y;
}

typedef unsigned long long u64;
__device__ __forceinline__ u64 pack2(float x, float y) {
    u64 r;
    asm("mov.b64 %0, {%1,%2};" : "=l"(r) : "f"(x), "f"(y));
    return r;
}
__device__ __forceinline__ float2 unpack2(u64 v) {
    float2 f;
    asm("mov.b64 {%0,%1}, %2;" : "=f"(f.x), "=f"(f.y) : "l"(v));
    return f;
}
// packed 2xfp32 FMA (FFMA2): acc = a*b + acc
__device__ __forceinline__ void fma2(u64& acc, u64 a, u64 b) {
    asm("fma.rn.f32x2 %0, %1, %2, %3;" : "=l"(acc) : "l"(a), "l"(b), "l"(acc));
}
// packed 2xfp32 ADD
__device__ __forceinline__ u64 add2(u64 a, u64 b) {
    u64 r;
    asm("add.rn.f32x2 %0, %1, %2;" : "=l"(r) : "l"(a), "l"(b));
    return r;
}

__device__ __forceinline__ void cp16(void* smem, const void* gmem) {
    uint32_t s = (uint32_t)__cvta_generic_to_shared(smem);
    asm volatile("cp.async.cg.shared.global [%0], [%1], 16;" :: "r"(s), "l"(gmem));
}
__device__ __forceinline__ void cp_commit() {
    asm volatile("cp.async.commit_group;");
}
template <int N>
__device__ __forceinline__ void cp_wait() {
    asm volatile("cp.async.wait_group %0;" :: "n"(N));
}

__device__ __forceinline__ void mma_bf16(float* d,
                                         uint32_t a0, uint32_t a1, uint32_t a2, uint32_t a3,
                                         uint32_t b0, uint32_t b1) {
    asm("mma.sync.aligned.m16n8k16.row.col.f32.bf16.bf16.f32 "
        "{%0,%1,%2,%3}, {%4,%5,%6,%7}, {%8,%9}, {%0,%1,%2,%3};"
        : "+f"(d[0]), "+f"(d[1]), "+f"(d[2]), "+f"(d[3])
        : "r"(a0), "r"(a1), "r"(a2), "r"(a3), "r"(b0), "r"(b1));
}

// Shared-tile MMA over one [128m x 32k] x [128n x 32k] chunk.
#define TPAD 40
__device__ __forceinline__ void mma_tile(const __nv_bfloat16* As,
                                         const __nv_bfloat16* Bs,
                                         float acc[2][8][4]) {
    const int lane = threadIdx.x & 31;
    const int warp = threadIdx.x >> 5;
    const int wm = warp >> 1;
    const int wn = warp & 1;
    const int lr = lane >> 2;
    const int lc = (lane & 3) * 2;
#pragma unroll
    for (int kk = 0; kk < 32; kk += 16) {
        uint32_t a[2][4];
#pragma unroll
        for (int mi = 0; mi < 2; mi++) {
            const __nv_bfloat16* p = As + (wm * 32 + mi * 16 + lr) * TPAD + kk + lc;
            a[mi][0] = *(const uint32_t*)p;
            a[mi][1] = *(const uint32_t*)(p + 8 * TPAD);
            a[mi][2] = *(const uint32_t*)(p + 8);
            a[mi][3] = *(const uint32_t*)(p + 8 * TPAD + 8);
        }
        uint32_t b[8][2];
#pragma unroll
        for (int ni = 0; ni < 8; ni++) {
            const __nv_bfloat16* p = Bs + (wn * 64 + ni * 8 + lr) * TPAD + kk + lc;
            b[ni][0] = *(const uint32_t*)p;
            b[ni][1] = *(const uint32_t*)(p + 8);
        }
#pragma unroll
        for (int mi = 0; mi < 2; mi++)
#pragma unroll
            for (int ni = 0; ni < 8; ni++)
                mma_bf16(acc[mi][ni], a[mi][0], a[mi][1], a[mi][2], a[mi][3],
                         b[ni][0], b[ni][1]);
    }
}

// ---------------------------------------------------------------------------
// K0: convert B, C to bf16
// ---------------------------------------------------------------------------
__global__ void k0_convert(const float* __restrict__ B, const float* __restrict__ C) {
    int idx = blockIdx.x * 256 + threadIdx.x;
    if (idx < DS * DM) g_Bbf[idx] = __float2bfloat16(B[idx]);
    if (idx < DM * DS) g_Cbf[idx] = __float2bfloat16(C[idx]);
}

// ---------------------------------------------------------------------------
// K1: xB = x @ B^T.  Grid: 256 CTAs (m-tiles of 128). N = 128 (one tile).
// ---------------------------------------------------------------------------
__global__ void __launch_bounds__(256) k1_xB(const float* __restrict__ x) {
    __shared__ __nv_bfloat16 As[128 * TPAD];
    __shared__ __nv_bfloat16 Bs[128 * TPAD];
    const int t = threadIdx.x;
    const int m0 = blockIdx.x * 128;

    float acc[2][8][4];
#pragma unroll
    for (int i = 0; i < 2; i++)
#pragma unroll
        for (int j = 0; j < 8; j++)
#pragma unroll
            for (int k = 0; k < 4; k++) acc[i][j][k] = 0.f;

    for (int kt = 0; kt < DM; kt += 32) {
#pragma unroll
        for (int pass = 0; pass < 4; pass++) {
            int r = pass * 32 + (t >> 3);
            int c = (t & 7) * 4;
            float4 v = *(const float4*)(x + (size_t)(m0 + r) * DM + kt + c);
            __nv_bfloat162 p0 = __floats2bfloat162_rn(v.x, v.y);
            __nv_bfloat162 p1 = __floats2bfloat162_rn(v.z, v.w);
            *(__nv_bfloat162*)&As[r * TPAD + c]     = p0;
            *(__nv_bfloat162*)&As[r * TPAD + c + 2] = p1;
        }
        {
            int r = t >> 1;
            int half = t & 1;
            const __nv_bfloat16* src = g_Bbf + r * DM + kt + half * 16;
            uint4 v0 = *(const uint4*)(src);
            uint4 v1 = *(const uint4*)(src + 8);
            *(uint4*)&Bs[r * TPAD + half * 16]     = v0;
            *(uint4*)&Bs[r * TPAD + half * 16 + 8] = v1;
        }
        __syncthreads();
        mma_tile(As, Bs, acc);
        __syncthreads();
    }

    const int lane = t & 31, warp = t >> 5;
    const int wm = warp >> 1, wn = warp & 1;
    const int lr = lane >> 2, lc = (lane & 3) * 2;
#pragma unroll
    for (int mi = 0; mi < 2; mi++)
#pragma unroll
        for (int ni = 0; ni < 8; ni++) {
            int row = m0 + wm * 32 + mi * 16 + lr;
            int col = wn * 64 + ni * 8 + lc;
            float* o0 = g_xB + (size_t)row * DS + col;
            float* o1 = g_xB + (size_t)(row + 8) * DS + col;
            *(float2*)o0 = make_float2(acc[mi][ni][0], acc[mi][ni][1]);
            *(float2*)o1 = make_float2(acc[mi][ni][2], acc[mi][ni][3]);
        }
}

// ---------------------------------------------------------------------------
// K2: recurrence. 16 CTAs (one per batch) x 128 threads.
// Thread t owns output element t: A row t in registers (64 f32x2),
// reads full state via broadcast LDS.128, no shuffles, no bank conflicts.
// xB double-buffered via cp.async in CH-step chunks.
// ---------------------------------------------------------------------------
__global__ void __launch_bounds__(128, 1) k2_scan(const float* __restrict__ A) {
    const int b = blockIdx.x;
    const int t = threadIdx.x;

    __shared__ float s_sh[2][DS];
    __shared__ float xb_sh[2][CH * DS];    // 2 x 8KB

    // A[t][0..127] as 64 packed f32x2 (128 registers)
    u64 a[64];
#pragma unroll
    for (int u = 0; u < 64; u++) {
        float2 v = *(const float2*)(A + t * DS + 2 * u);
        a[u] = pack2(v.x, v.y);
    }

    const float* xb = g_xB + (size_t)b * SEQ * DS;
    __nv_bfloat16* so = g_states + (size_t)b * SEQ * DS;

    // preload chunks 0 and 1 (each 8KB: 128 threads x 4 x 16B)
#pragma unroll
    for (int q = 0; q < 4; q++)
        cp16(&xb_sh[0][(q * DS + t) * 4], xb + (q * DS + t) * 4);
    cp_commit();
#pragma unroll
    for (int q = 0; q < 4; q++)
        cp16(&xb_sh[1][(q * DS + t) * 4], xb + CH * DS + (q * DS + t) * 4);
    cp_commit();

    s_sh[0][t] = 0.f;
    s_sh[1][t] = 0.f;
    __syncthreads();

    for (int c = 0; c < SEQ / CH; c++) {
        cp_wait<1>();          // chunk c resident
        __syncthreads();

        const float* xbc = xb_sh[c & 1];
#pragma unroll 1
        for (int k = 0; k < CH; k++) {
            const int tt = c * CH + k;
            const ulonglong2* sv = (const ulonglong2*)(s_sh[tt & 1]);
            u64 ac0 = 0ull, ac1 = 0ull, ac2 = 0ull, ac3 = 0ull;
            u64 ac4 = 0ull, ac5 = 0ull, ac6 = 0ull, ac7 = 0ull;
#pragma unroll
            for (int u = 0; u < 32; u += 4) {
                ulonglong2 w0 = sv[u + 0];
                ulonglong2 w1 = sv[u + 1];
                ulonglong2 w2 = sv[u + 2];
                ulonglong2 w3 = sv[u + 3];
                fma2(ac0, a[2 * u + 0], w0.x);
                fma2(ac1, a[2 * u + 1], w0.y);
                fma2(ac2, a[2 * u + 2], w1.x);
                fma2(ac3, a[2 * u + 3], w1.y);
                fma2(ac4, a[2 * u + 4], w2.x);
                fma2(ac5, a[2 * u + 5], w2.y);
                fma2(ac6, a[2 * u + 6], w3.x);
                fma2(ac7, a[2 * u + 7], w3.y);
            }
            u64 s0 = add2(add2(ac0, ac1), add2(ac2, ac3));
            u64 s1 = add2(add2(ac4, ac5), add2(ac6, ac7));
            float2 f = unpack2(add2(s0, s1));
            float s = tanh_fast(f.x + f.y + xbc[k * DS + t]);
            s_sh[(tt + 1) & 1][t] = s;
            so[tt * DS + t] = __float2bfloat16(s);
            __syncthreads();
        }

        // prefetch chunk c+2 into the buffer just consumed
        if (c + 2 < SEQ / CH) {
            const float* src = xb + (size_t)(c + 2) * CH * DS;
#pragma unroll
            for (int q = 0; q < 4; q++)
                cp16(&xb_sh[c & 1][(q * DS + t) * 4], src + (q * DS + t) * 4);
        }
        cp_commit();
    }
}

// ---------------------------------------------------------------------------
// K3: out = states @ C^T.  Grid: (256 m-tiles, 8 n-tiles). K = 128.
// ---------------------------------------------------------------------------
__global__ void __launch_bounds__(256) k3_out() {
    __shared__ __nv_bfloat16 As[128 * TPAD];
    __shared__ __nv_bfloat16 Bs[128 * TPAD];
    const int t = threadIdx.x;
    const int m0 = blockIdx.x * 128;
    const int n0 = blockIdx.y * 128;

    float acc[2][8][4];
#pragma unroll
    for (int i = 0; i < 2; i++)
#pragma unroll
        for (int j = 0; j < 8; j++)
#pragma unroll
            for (int k = 0; k < 4; k++) acc[i][j][k] = 0.f;

    for (int kt = 0; kt < DS; kt += 32) {
        {
            int r = t >> 1;
            int half = t & 1;
            const __nv_bfloat16* src = g_states + (size_t)(m0 + r) * DS + kt + half * 16;
            uint4 v0 = *(const uint4*)(src);
            uint4 v1 = *(const uint4*)(src + 8);
            *(uint4*)&As[r * TPAD + half * 16]     = v0;
            *(uint4*)&As[r * TPAD + half * 16 + 8] = v1;
        }
        {
            int r = t >> 1;
            int half = t & 1;
            const __nv_bfloat16* src = g_Cbf + (n0 + r) * DS + kt + half * 16;
            uint4 v0 = *(const uint4*)(src);
            uint4 v1 = *(const uint4*)(src + 8);
            *(uint4*)&Bs[r * TPAD + half * 16]     = v0;
            *(uint4*)&Bs[r * TPAD + half * 16 + 8] = v1;
        }
        __syncthreads();
        mma_tile(As, Bs, acc);
        __syncthreads();
    }

    const int lane = t & 31, warp = t >> 5;
    const int wm = warp >> 1, wn = warp & 1;
    const int lr = lane >> 2, lc = (lane & 3) * 2;
#pragma unroll
    for (int mi = 0; mi < 2; mi++)
#pragma unroll
        for (int ni = 0; ni < 8; ni++) {
            int row = m0 + wm * 32 + mi * 16 + lr;
            int col = n0 + wn * 64 + ni * 8 + lc;
            float* o0 = g_t + (size_t)row * DM + col;
            float* o1 = g_t + (size_t)(row + 8) * DM + col;
            *(float2*)o0 = make_float2(acc[mi][ni][0], acc[mi][ni][1]);
            *(float2*)o1 = make_float2(acc[mi][ni][2], acc[mi][ni][3]);
        }
}

// ---------------------------------------------------------------------------
// K4: y = LN(out + D*x + x) * gamma + beta.  One CTA (256 thr) per row.
// ---------------------------------------------------------------------------
__global__ void __launch_bounds__(256) k4_ln(const float* __restrict__ x,
                                             const float* __restrict__ D,
                                             const float* __restrict__ gamma,
                                             const float* __restrict__ beta,
                                             float* __restrict__ y) {
    const int m = blockIdx.x;
    const int t = threadIdx.x;
    const int c = t * 4;

    float4 o4 = *(const float4*)(g_t + (size_t)m * DM + c);
    float4 x4 = *(const float4*)(x + (size_t)m * DM + c);
    float4 d4 = *(const float4*)(D + c);

    float4 v;
    v.x = o4.x + d4.x * x4.x + x4.x;
    v.y = o4.y + d4.y * x4.y + x4.y;
    v.z = o4.z + d4.z * x4.z + x4.z;
    v.w = o4.w + d4.w * x4.w + x4.w;

    float s = v.x + v.y + v.z + v.w;
    float q = v.x * v.x + v.y * v.y + v.z * v.z + v.w * v.w;
#pragma unroll
    for (int o = 16; o > 0; o >>= 1) {
        s += __shfl_xor_sync(0xffffffffu, s, o);
        q += __shfl_xor_sync(0xffffffffu, q, o);
    }
    __shared__ float ss[8], qq[8];
    __shared__ float mu_s, rs_s;
    if ((t & 31) == 0) { ss[t >> 5] = s; qq[t >> 5] = q; }
    __syncthreads();
    if (t == 0) {
        float S = 0.f, Q = 0.f;
#pragma unroll
        for (int w = 0; w < 8; w++) { S += ss[w]; Q += qq[w]; }
        float mu = S * (1.f / DM);
        float var = Q * (1.f / DM) - mu * mu;
        mu_s = mu;
        rs_s = rsqrtf(var + LN_EPS);
    }
    __syncthreads();
    float mu = mu_s, rs = rs_s;

    float4 g4 = *(const float4*)(gamma + c);
    float4 b4 = *(const float4*)(beta + c);
    float4 out;
    out.x = (v.x - mu) * rs * g4.x + b4.x;
    out.y = (v.y - mu) * rs * g4.y + b4.y;
    out.z = (v.z - mu) * rs * g4.z + b4.z;
    out.w = (v.w - mu) * rs * g4.w + b4.w;
    *(float4*)(y + (size_t)m * DM + c) = out;
}

// ---------------------------------------------------------------------------
extern "C" void kernel_launch(void* const* d_in, const int* in_sizes, int n_in,
                              void* d_out, int out_size) {
    const float* x     = (const float*)d_in[0];
    const float* A     = (const float*)d_in[1];
    const float* B     = (const float*)d_in[2];
    const float* C     = (const float*)d_in[3];
    const float* D     = (const float*)d_in[4];
    const float* gamma = (const float*)d_in[5];
    const float* beta  = (const float*)d_in[6];
    float* y = (float*)d_out;

    k0_convert<<<512, 256>>>(B, C);
    k1_xB<<<MTOT / 128, 256>>>(x);
    k2_scan<<<BATCH, 128>>>(A);
    k3_out<<<dim3(MTOT / 128, DM / 128), 256>>>();
    k4_ln<<<MTOT, 256>>>(x, D, gamma, beta, y);
}